// round 9
// baseline (speedup 1.0000x reference)
#include <cuda_runtime.h>
#include <cuda_bf16.h>
#include <cstdint>

#define N_NODES 50000
#define D_FEAT  128
#define N_EDGES 600000
#define CAP     96   // Poisson(12) in-degree: P(deg > 96) ~ 1e-60 -> never overflows

// static scratch (no cudaMalloc allowed). Zero-initialized at module load;
// agg_kernel consumes-and-resets g_cnt at block start, so the correctness
// call and every graph replay start from zeroed counters.
__device__ int g_cnt[N_NODES];
__device__ int g_bucket[N_NODES * CAP];

// ---------------------------------------------------------------------------
// Kernel 1: bin edges by destination. One thread per edge.
// Index dtype detected per-block by warp 0 via ballot over 32 int32 pairs:
// int64 values < 2^31 read as int32 pairs give (val, 0); for int32 data the
// odd words are random node ids, so all-32-lanes-consistent is conclusive.
// ---------------------------------------------------------------------------
__global__ void fill_kernel(const void* __restrict__ src_raw,
                            const void* __restrict__ dst_raw) {
    __shared__ int sh_is64;
    if (threadIdx.x < 32) {
        const int* p = (const int*)dst_raw;
        int lo = p[2 * threadIdx.x];
        int hi = p[2 * threadIdx.x + 1];
        bool ok = (hi == 0) && (lo >= 0) && (lo < N_NODES);
        unsigned m = __ballot_sync(0xffffffffu, ok);
        if (threadIdx.x == 0) sh_is64 = (m == 0xffffffffu) ? 1 : 0;
    }
    __syncthreads();
    int is64 = sh_is64;

    int e = blockIdx.x * blockDim.x + threadIdx.x;
    if (e >= N_EDGES) return;

    long long s, d;
    if (is64) {
        s = __ldg((const long long*)src_raw + e);
        d = __ldg((const long long*)dst_raw + e);
    } else {
        s = __ldg((const int*)src_raw + e);
        d = __ldg((const int*)dst_raw + e);
    }
    if (s < 0 || s >= N_NODES || d < 0 || d >= N_NODES) return;

    int pos = atomicAdd(&g_cnt[(int)d], 1);
    if (pos < CAP) g_bucket[(int)d * CAP + pos] = (int)s;
}

// ---------------------------------------------------------------------------
// Kernel 2: one warp per node, 8 nodes per 256-thread block (grid is exact:
// 50000 = 6250 * 8). Threads 0-7 read the block's 8 counters into shared and
// zero them in the same instruction slot (consume-and-reset); the barrier
// orders the reset before any warp uses its count. The gather loop is the
// proven 26.7us form: leaf kernel, (emb, out) args only, no stores after the
// output write (R6-R8 lessons).
// ---------------------------------------------------------------------------
__global__ void agg_kernel(const float* __restrict__ emb,
                           float* __restrict__ out) {
    __shared__ int sh_c[8];
    int t = threadIdx.x;
    if (t < 8) {
        int n = blockIdx.x * 8 + t;      // always < N_NODES (exact grid)
        int cc = g_cnt[n];
        sh_c[t] = cc;
        g_cnt[n] = 0;                     // reset for next replay
    }
    __syncthreads();

    int warp = t >> 5;
    int lane = t & 31;
    int node = blockIdx.x * 8 + warp;
    int c = sh_c[warp];

    int m = (c < CAP) ? c : CAP;          // clamp (never hit for this dataset)
    const int* bk = g_bucket + node * CAP;

    float4 acc = make_float4(0.f, 0.f, 0.f, 0.f);

    for (int base = 0; base < m; base += 32) {
        int lim = m - base; if (lim > 32) lim = 32;
        int s_l = (lane < lim) ? bk[base + lane] : 0;
        #pragma unroll 4
        for (int e = 0; e < lim; e++) {
            int s = __shfl_sync(0xffffffffu, s_l, e);
            float4 v = __ldg((const float4*)(emb + (long long)s * D_FEAT) + lane);
            acc.x += v.x; acc.y += v.y; acc.z += v.z; acc.w += v.w;
        }
    }

    float inv = (c > 0) ? (1.0f / (float)c) : 0.0f;
    acc.x *= inv; acc.y *= inv; acc.z *= inv; acc.w *= inv;
    ((float4*)out)[node * (D_FEAT / 4) + lane] = acc;
}

// ---------------------------------------------------------------------------
extern "C" void kernel_launch(void* const* d_in, const int* in_sizes, int n_in,
                              void* d_out, int out_size) {
    const float* emb = (const float*)d_in[0];
    const void*  src = d_in[1];
    const void*  dst = d_in[2];
    float* out = (float*)d_out;

    fill_kernel<<<(N_EDGES + 255) / 256, 256>>>(src, dst);
    agg_kernel<<<N_NODES / 8, 256>>>(emb, out);   // 6250 blocks, exact
}

// round 10
// speedup vs baseline: 1.0553x; 1.0553x over previous
#include <cuda_runtime.h>
#include <cuda_bf16.h>
#include <cstdint>

#define N_NODES 50000
#define D_FEAT  128
#define N_EDGES 600000
#define CAP     96   // Poisson(12) in-degree: P(deg > 96) ~ 1e-60 -> never overflows

// static scratch (no cudaMalloc allowed)
__device__ int g_cnt[N_NODES];
__device__ int g_bucket[N_NODES * CAP];
__device__ int g_is64;

// ---------------------------------------------------------------------------
// Kernel 1: zero counts (vectorized) + dtype detect by warp ballot in block 0.
// int64 values < 2^31 read as int32 pairs give (val, 0); for int32 data the
// odd words are random node ids, so 32-lanes-consistent is conclusive.
// ---------------------------------------------------------------------------
__global__ void init_kernel(const int* __restrict__ idx_as_i32) {
    int i = blockIdx.x * blockDim.x + threadIdx.x;
    // 50000 = 12500 int4
    if (i < N_NODES / 4) {
        ((int4*)g_cnt)[i] = make_int4(0, 0, 0, 0);
    }
    if (blockIdx.x == 0 && threadIdx.x < 32) {
        int lo = idx_as_i32[2 * threadIdx.x];
        int hi = idx_as_i32[2 * threadIdx.x + 1];
        bool ok = (hi == 0) && (lo >= 0) && (lo < N_NODES);
        unsigned m = __ballot_sync(0xffffffffu, ok);
        if (threadIdx.x == 0) g_is64 = (m == 0xffffffffu) ? 1 : 0;
    }
}

// ---------------------------------------------------------------------------
// Kernel 2: bin edges by destination. One thread per edge (proven R4 form:
// uniform g_is64 load, no block barrier).
// ---------------------------------------------------------------------------
__global__ void fill_kernel(const void* __restrict__ src_raw,
                            const void* __restrict__ dst_raw) {
    int e = blockIdx.x * blockDim.x + threadIdx.x;
    if (e >= N_EDGES) return;

    long long s, d;
    if (g_is64) {
        s = __ldg((const long long*)src_raw + e);
        d = __ldg((const long long*)dst_raw + e);
    } else {
        s = __ldg((const int*)src_raw + e);
        d = __ldg((const int*)dst_raw + e);
    }
    if (s < 0 || s >= N_NODES || d < 0 || d >= N_NODES) return;

    int pos = atomicAdd(&g_cnt[(int)d], 1);
    if (pos < CAP) g_bucket[(int)d * CAP + pos] = (int)s;
}

// ---------------------------------------------------------------------------
// Kernel 3: one warp per node. Gather-reduce bucketed sources (L2-resident
// table), write the mean once. EXACT R4 form — leaf kernel, (emb,out) args,
// direct count read, NO reset/barrier/extra stores (R6-R9: any such
// perturbation costs 6-39us by serializing the gather loop's load batching).
// ---------------------------------------------------------------------------
__global__ void agg_kernel(const float* __restrict__ emb,
                           float* __restrict__ out) {
    int gtid = blockIdx.x * blockDim.x + threadIdx.x;
    int node = gtid >> 5;
    int lane = gtid & 31;
    if (node >= N_NODES) return;

    int c = g_cnt[node];
    int m = (c < CAP) ? c : CAP;
    const int* bk = g_bucket + node * CAP;

    float4 acc = make_float4(0.f, 0.f, 0.f, 0.f);

    for (int base = 0; base < m; base += 32) {
        int lim = m - base; if (lim > 32) lim = 32;
        int s_l = (lane < lim) ? bk[base + lane] : 0;
        #pragma unroll 4
        for (int e = 0; e < lim; e++) {
            int s = __shfl_sync(0xffffffffu, s_l, e);
            float4 v = __ldg((const float4*)(emb + (long long)s * D_FEAT) + lane);
            acc.x += v.x; acc.y += v.y; acc.z += v.z; acc.w += v.w;
        }
    }

    float inv = (c > 0) ? (1.0f / (float)c) : 0.0f;
    acc.x *= inv; acc.y *= inv; acc.z *= inv; acc.w *= inv;
    ((float4*)out)[node * (D_FEAT / 4) + lane] = acc;
}

// ---------------------------------------------------------------------------
extern "C" void kernel_launch(void* const* d_in, const int* in_sizes, int n_in,
                              void* d_out, int out_size) {
    const float* emb = (const float*)d_in[0];
    const void*  src = d_in[1];
    const void*  dst = d_in[2];
    float* out = (float*)d_out;

    init_kernel<<<(N_NODES / 4 + 255) / 256, 256>>>((const int*)dst);
    fill_kernel<<<(N_EDGES + 255) / 256, 256>>>(src, dst);
    {
        long long total_threads = (long long)N_NODES * 32;
        agg_kernel<<<(int)((total_threads + 255) / 256), 256>>>(emb, out);
    }
}